// round 3
// baseline (speedup 1.0000x reference)
#include <cuda_runtime.h>
#include <cstdint>

// Problem constants
#define BB 8
#define NN 16
#define SS 118
#define AA 10
#define DD 128      // S + A
#define DKK 64
#define HH 2

// Scratch (no allocations allowed)
__device__ float g_base[BB*HH*NN*DKK];        // base[b,h,i,e] = sum_k w[b,h,i,k]*avA[b,h,k,e]
__device__ float g_diff[BB*HH*NN*DKK];        // (avP-avA)[b,h,j,e]
__device__ float g_nm[BB*HH*NN*NN*DKK];       // mean_k noise[b,h,i,j,k,e]

// ---------------------------------------------------------------------------
// Threefry2x32 with key = PRNGKey(42) = (0, 42). ks0=0 adds folded out.
// ---------------------------------------------------------------------------
__device__ __forceinline__ void threefry(uint32_t c0, uint32_t c1,
                                         uint32_t& o0, uint32_t& o1) {
  const uint32_t ks1 = 42u;
  const uint32_t ks2 = 42u ^ 0x1BD11BDAu;
  uint32_t x0 = c0;          // + ks0 (=0)
  uint32_t x1 = c1 + ks1;
#define TFR(r) { x0 += x1; x1 = __funnelshift_l(x1, x1, (r)); x1 ^= x0; }
  TFR(13) TFR(15) TFR(26) TFR(6)   x0 += ks1; x1 += ks2 + 1u;
  TFR(17) TFR(29) TFR(16) TFR(24)  x0 += ks2; x1 += 2u;          // + ks0
  TFR(13) TFR(15) TFR(26) TFR(6)   /* x0 += ks0 */ x1 += ks1 + 3u;
  TFR(17) TFR(29) TFR(16) TFR(24)  x0 += ks1; x1 += ks2 + 4u;
  TFR(13) TFR(15) TFR(26) TFR(6)   x0 += ks2; x1 += 5u;          // + ks0
#undef TFR
  o0 = x0; o1 = x1;
}

// Partitionable-threefry 32-bit draw for flat index idx (< 2^32 => c0 = 0).
// bits = out0 ^ out1  (jax _threefry_random_bits_partitionable, bit_width 32)
__device__ __forceinline__ float tf_unif(uint32_t idx) {
  uint32_t o0, o1;
  threefry(0u, idx, o0, o1);
  uint32_t bits = o0 ^ o1;
  return __uint_as_float((bits >> 9) | 0x3f800000u);   // in [1,2)
}

// ---------------------------------------------------------------------------
// Stage 1: blocks 0..7     -> attention math per batch b
//          blocks 8..1031  -> noise mean computation (input independent)
// ---------------------------------------------------------------------------
__global__ void __launch_bounds__(256) k_stage1(
    const float* __restrict__ states, const float* __restrict__ policies,
    const float* __restrict__ actions, const float* __restrict__ Wk,
    const float* __restrict__ Wq, const float* __restrict__ Wv,
    float* __restrict__ out)
{
  int tid = threadIdx.x;

  if (blockIdx.x >= 8) {
    // ---------------- noise: mean over k of uniform noise -----------------
    // flat idx = ((((b*H+h)*N+i)*N+j)*N+k)*DK+e ; unit = ((b*H+h)*N+i)*N+j
    // Partitionable threefry: counter = 64-bit flat index (hi = 0 here),
    // one call per element, bits = o0 ^ o1.
    int unit = (blockIdx.x - 8) * 4 + (tid >> 6);   // 0..4095 (b,h,i,j)
    int e = tid & 63;
    uint32_t base = (uint32_t)unit * 1024u + (uint32_t)e;
    float s = 0.f;
#pragma unroll
    for (int k = 0; k < 16; ++k)
      s += tf_unif(base + (uint32_t)(k * 64));
    // mean((u-0.5)*0.1) = (mean(f) - 1.5)*0.1  with f in [1,2)
    g_nm[unit * 64 + e] = (s * 0.0625f - 1.5f) * 0.1f;
    return;
  }

  // ---------------- attention math for batch b ----------------
  int b = blockIdx.x;
  __shared__ float oa[NN][DD];                 // concat(state, action)
  __shared__ float op[NN][DD];                 // concat(state, policy)
  __shared__ float kbuf[HH][NN][DKK];          // k[h][i][e]
  __shared__ float qT[HH][DKK][NN];            // q transposed: [h][e][j]
  __shared__ float avA[HH][NN][DKK];           // tanh(oa . Wv)
  __shared__ float wsm[HH][NN][NN];            // scores -> softmax weights

  // load / build oa, op
  for (int idx = tid; idx < NN * DD; idx += 256) {
    int n = idx >> 7, d = idx & 127;
    float oav, opv;
    if (d < SS) { float s = states[(b * NN + n) * SS + d]; oav = s; opv = s; }
    else {
      oav = actions [(b * NN + n) * AA + (d - SS)];
      opv = policies[(b * NN + n) * AA + (d - SS)];
    }
    oa[n][d] = oav; op[n][d] = opv;
  }
  __syncthreads();

  int e  = tid & 63;   // output feature
  int ng = tid >> 6;   // row group 0..3

  // K and Q projections: thread (e, ng) covers rows n = ng*4..ng*4+3, both h
  for (int h = 0; h < 2; ++h) {
    const float4* wk4 = (const float4*)(Wk + (h * 64 + e) * 128);
    const float4* wq4 = (const float4*)(Wq + (h * 64 + e) * 128);
    float sk[4] = {0,0,0,0}, sq[4] = {0,0,0,0};
#pragma unroll 8
    for (int d4 = 0; d4 < 32; ++d4) {
      float4 wkv = wk4[d4];
      float4 wqv = wq4[d4];
#pragma unroll
      for (int t = 0; t < 4; ++t) {
        int n = ng * 4 + t;
        float4 a = *(const float4*)&oa[n][d4 * 4];
        sk[t] += a.x * wkv.x + a.y * wkv.y + a.z * wkv.z + a.w * wkv.w;
        sq[t] += a.x * wqv.x + a.y * wqv.y + a.z * wqv.z + a.w * wqv.w;
      }
    }
#pragma unroll
    for (int t = 0; t < 4; ++t) {
      int n = ng * 4 + t;
      kbuf[h][n][e] = sk[t];
      qT[h][e][n]   = sq[t];
    }
  }
  __syncthreads();

  // scores[b,h,i,j] = q[b,h,j] . k[b,h,i] / sqrt(64)
  for (int o = tid; o < 512; o += 256) {
    int h = o >> 8, i = (o >> 4) & 15, j = o & 15;
    float s = 0.f;
#pragma unroll 16
    for (int ee = 0; ee < 64; ++ee)
      s += qT[h][ee][j] * kbuf[h][i][ee];
    wsm[h][i][j] = s * 0.125f;
  }
  __syncthreads();

  // softmax over j (one thread per (h,i) row), write weight output
  if (tid < 32) {
    int h = tid >> 4, i = tid & 15;
    float m = -1e30f;
#pragma unroll
    for (int j = 0; j < 16; ++j) m = fmaxf(m, wsm[h][i][j]);
    float sum = 0.f, ex[16];
#pragma unroll
    for (int j = 0; j < 16; ++j) { ex[j] = expf(wsm[h][i][j] - m); sum += ex[j]; }
    float inv = 1.f / sum;
#pragma unroll
    for (int j = 0; j < 16; ++j) {
      float w = ex[j] * inv;
      wsm[h][i][j] = w;
      out[2048 + ((b * 2 + h) * 16 + i) * 16 + j] = w;   // weight output
    }
  }
  __syncthreads();

  // value projections: avA = tanh(oa.Wv), diff = tanh(op.Wv) - avA
  for (int h = 0; h < 2; ++h) {
    const float4* wv4 = (const float4*)(Wv + (h * 64 + e) * 128);
    float sA[4] = {0,0,0,0}, sP[4] = {0,0,0,0};
#pragma unroll 8
    for (int d4 = 0; d4 < 32; ++d4) {
      float4 w = wv4[d4];
#pragma unroll
      for (int t = 0; t < 4; ++t) {
        int n = ng * 4 + t;
        float4 a = *(const float4*)&oa[n][d4 * 4];
        float4 p = *(const float4*)&op[n][d4 * 4];
        sA[t] += a.x * w.x + a.y * w.y + a.z * w.z + a.w * w.w;
        sP[t] += p.x * w.x + p.y * w.y + p.z * w.z + p.w * w.w;
      }
    }
#pragma unroll
    for (int t = 0; t < 4; ++t) {
      int n = ng * 4 + t;
      float ta = tanhf(sA[t]);
      float tp = tanhf(sP[t]);
      avA[h][n][e] = ta;
      g_diff[((b * 2 + h) * 16 + n) * 64 + e] = tp - ta;
    }
  }
  __syncthreads();

  // base[b,h,i,e] = sum_k w[b,h,i,k] * avA[b,h,k,e]
  for (int o = tid; o < 2048; o += 256) {
    int h = o >> 10, i = (o >> 6) & 15, ee = o & 63;
    float s = 0.f;
#pragma unroll
    for (int k = 0; k < 16; ++k)
      s += wsm[h][i][k] * avA[h][k][ee];
    g_base[((b * 2 + h) * 16 + i) * 64 + ee] = s;
  }
}

// ---------------------------------------------------------------------------
// Stage 2: per (b,i,j): assemble x[128], MLP 128->64 (leaky relu) ->1
// ---------------------------------------------------------------------------
__global__ void __launch_bounds__(128) k_mlp(
    const float* __restrict__ W1, const float* __restrict__ W2,
    float* __restrict__ out)
{
  int blk = blockIdx.x;                  // 0..2047
  int b = blk >> 8, i = (blk >> 4) & 15, j = blk & 15;
  __shared__ float x[128];
  __shared__ float red[2];
  int t = threadIdx.x;
  {
    int h = t >> 6, e = t & 63;
    float w  = out[2048 + ((b * 2 + h) * 16 + i) * 16 + j];
    float bs = g_base[((b * 2 + h) * 16 + i) * 64 + e];
    float df = g_diff[((b * 2 + h) * 16 + j) * 64 + e];
    float nm = g_nm[(((b * 2 + h) * 16 + i) * 16 + j) * 64 + e];
    x[t] = (bs + w * df) * 0.0625f + nm;   // /16 + noise mean
  }
  __syncthreads();
  float r = 0.f;
  if (t < 64) {
    const float4* w1 = (const float4*)(W1 + t * 128);
    const float4* x4 = (const float4*)x;
    float s = 0.f;
#pragma unroll 8
    for (int c = 0; c < 32; ++c) {
      float4 wv = w1[c]; float4 xv = x4[c];
      s += wv.x * xv.x + wv.y * xv.y + wv.z * xv.z + wv.w * xv.w;
    }
    s = s > 0.f ? s : 0.01f * s;           // leaky_relu(0.01)
    r = s * W2[t];
  }
#pragma unroll
  for (int o = 16; o > 0; o >>= 1) r += __shfl_down_sync(0xffffffffu, r, o);
  if ((t & 31) == 0 && t < 64) red[t >> 5] = r;
  __syncthreads();
  if (t == 0) out[(b * 16 + i) * 16 + j] = red[0] + red[1];
}

// ---------------------------------------------------------------------------
extern "C" void kernel_launch(void* const* d_in, const int* in_sizes, int n_in,
                              void* d_out, int out_size) {
  const float* states   = (const float*)d_in[0];
  const float* policies = (const float*)d_in[1];
  const float* actions  = (const float*)d_in[2];
  const float* Wk       = (const float*)d_in[3];
  const float* Wq       = (const float*)d_in[4];
  const float* Wv       = (const float*)d_in[5];
  const float* W1       = (const float*)d_in[6];
  const float* W2       = (const float*)d_in[7];
  float* out = (float*)d_out;

  // 8 attention blocks + 1024 noise blocks, run concurrently in one launch
  k_stage1<<<8 + 1024, 256>>>(states, policies, actions, Wk, Wq, Wv, out);
  // consumes weight (in out), base/diff/noise scratch
  k_mlp<<<2048, 128>>>(W1, W2, out);
}

// round 4
// speedup vs baseline: 1.1887x; 1.1887x over previous
#include <cuda_runtime.h>
#include <cstdint>

// Problem constants
#define BB 8
#define NN 16
#define SS 118
#define AA 10
#define DD 128      // S + A
#define DKK 64
#define HH 2

// Scratch (no allocations allowed)
__device__ float g_base[BB*HH*NN*DKK];        // base[b,h,i,e] = sum_k w[b,h,i,k]*avA[b,h,k,e]
__device__ float g_diff[BB*HH*NN*DKK];        // (avP-avA)[b,h,j,e]
__device__ float g_nm[BB*HH*NN*NN*DKK];       // mean_k noise[b,h,i,j,k,e]

// ---------------------------------------------------------------------------
// Threefry2x32 with key = PRNGKey(42) = (0, 42). ks0=0 adds folded out.
// ---------------------------------------------------------------------------
__device__ __forceinline__ void threefry(uint32_t c0, uint32_t c1,
                                         uint32_t& o0, uint32_t& o1) {
  const uint32_t ks1 = 42u;
  const uint32_t ks2 = 42u ^ 0x1BD11BDAu;
  uint32_t x0 = c0;          // + ks0 (=0)
  uint32_t x1 = c1 + ks1;
#define TFR(r) { x0 += x1; x1 = __funnelshift_l(x1, x1, (r)); x1 ^= x0; }
  TFR(13) TFR(15) TFR(26) TFR(6)   x0 += ks1; x1 += ks2 + 1u;
  TFR(17) TFR(29) TFR(16) TFR(24)  x0 += ks2; x1 += 2u;          // + ks0
  TFR(13) TFR(15) TFR(26) TFR(6)   /* x0 += ks0 */ x1 += ks1 + 3u;
  TFR(17) TFR(29) TFR(16) TFR(24)  x0 += ks1; x1 += ks2 + 4u;
  TFR(13) TFR(15) TFR(26) TFR(6)   x0 += ks2; x1 += 5u;          // + ks0
#undef TFR
  o0 = x0; o1 = x1;
}

// Partitionable-threefry 32-bit draw for flat index idx (< 2^32 => c0 = 0).
// bits = out0 ^ out1  (jax _threefry_random_bits_partitionable, bit_width 32)
__device__ __forceinline__ float tf_unif(uint32_t idx) {
  uint32_t o0, o1;
  threefry(0u, idx, o0, o1);
  uint32_t bits = o0 ^ o1;
  return __uint_as_float((bits >> 9) | 0x3f800000u);   // in [1,2)
}

// ---------------------------------------------------------------------------
// Stage 1: blocks 0..7     -> attention math per batch b
//          blocks 8..1031  -> noise mean computation (input independent)
// ---------------------------------------------------------------------------
__global__ void __launch_bounds__(256) k_stage1(
    const float* __restrict__ states, const float* __restrict__ policies,
    const float* __restrict__ actions, const float* __restrict__ Wk,
    const float* __restrict__ Wq, const float* __restrict__ Wv,
    float* __restrict__ out)
{
  int tid = threadIdx.x;

  if (blockIdx.x >= 8) {
    // ---------------- noise: mean over k of uniform noise -----------------
    // flat idx = ((((b*H+h)*N+i)*N+j)*N+k)*DK+e ; unit = ((b*H+h)*N+i)*N+j
    // Partitionable threefry: counter = 64-bit flat index (hi = 0 here),
    // one call per element, bits = o0 ^ o1.
    int unit = (blockIdx.x - 8) * 4 + (tid >> 6);   // 0..4095 (b,h,i,j)
    int e = tid & 63;
    uint32_t base = (uint32_t)unit * 1024u + (uint32_t)e;
    float s = 0.f;
#pragma unroll
    for (int k = 0; k < 16; ++k)
      s += tf_unif(base + (uint32_t)(k * 64));
    // mean((u-0.5)*0.1) = (mean(f) - 1.5)*0.1  with f in [1,2)
    g_nm[unit * 64 + e] = (s * 0.0625f - 1.5f) * 0.1f;
    return;
  }

  // ---------------- attention math for batch b ----------------
  int b = blockIdx.x;
  __shared__ float oa[NN][DD];                 // concat(state, action)
  __shared__ float op[NN][DD];                 // concat(state, policy)
  __shared__ float kbuf[HH][NN][DKK];          // k[h][i][e]
  __shared__ float qT[HH][DKK][NN];            // q transposed: [h][e][j]
  __shared__ float avA[HH][NN][DKK];           // tanh(oa . Wv)
  __shared__ float wsm[HH][NN][NN];            // scores -> softmax weights

  // load / build oa, op
  for (int idx = tid; idx < NN * DD; idx += 256) {
    int n = idx >> 7, d = idx & 127;
    float oav, opv;
    if (d < SS) { float s = states[(b * NN + n) * SS + d]; oav = s; opv = s; }
    else {
      oav = actions [(b * NN + n) * AA + (d - SS)];
      opv = policies[(b * NN + n) * AA + (d - SS)];
    }
    oa[n][d] = oav; op[n][d] = opv;
  }
  __syncthreads();

  int e  = tid & 63;   // output feature
  int ng = tid >> 6;   // row group 0..3

  // K and Q projections: thread (e, ng) covers rows n = ng*4..ng*4+3, both h
  for (int h = 0; h < 2; ++h) {
    const float4* wk4 = (const float4*)(Wk + (h * 64 + e) * 128);
    const float4* wq4 = (const float4*)(Wq + (h * 64 + e) * 128);
    float sk[4] = {0,0,0,0}, sq[4] = {0,0,0,0};
#pragma unroll 8
    for (int d4 = 0; d4 < 32; ++d4) {
      float4 wkv = wk4[d4];
      float4 wqv = wq4[d4];
#pragma unroll
      for (int t = 0; t < 4; ++t) {
        int n = ng * 4 + t;
        float4 a = *(const float4*)&oa[n][d4 * 4];
        sk[t] += a.x * wkv.x + a.y * wkv.y + a.z * wkv.z + a.w * wkv.w;
        sq[t] += a.x * wqv.x + a.y * wqv.y + a.z * wqv.z + a.w * wqv.w;
      }
    }
#pragma unroll
    for (int t = 0; t < 4; ++t) {
      int n = ng * 4 + t;
      kbuf[h][n][e] = sk[t];
      qT[h][e][n]   = sq[t];
    }
  }
  __syncthreads();

  // scores[b,h,i,j] = q[b,h,j] . k[b,h,i] / sqrt(64)
  for (int o = tid; o < 512; o += 256) {
    int h = o >> 8, i = (o >> 4) & 15, j = o & 15;
    float s = 0.f;
#pragma unroll 16
    for (int ee = 0; ee < 64; ++ee)
      s += qT[h][ee][j] * kbuf[h][i][ee];
    wsm[h][i][j] = s * 0.125f;
  }
  __syncthreads();

  // softmax over j (one thread per (h,i) row), write weight output
  if (tid < 32) {
    int h = tid >> 4, i = tid & 15;
    float m = -1e30f;
#pragma unroll
    for (int j = 0; j < 16; ++j) m = fmaxf(m, wsm[h][i][j]);
    float sum = 0.f, ex[16];
#pragma unroll
    for (int j = 0; j < 16; ++j) { ex[j] = expf(wsm[h][i][j] - m); sum += ex[j]; }
    float inv = 1.f / sum;
#pragma unroll
    for (int j = 0; j < 16; ++j) {
      float w = ex[j] * inv;
      wsm[h][i][j] = w;
      out[2048 + ((b * 2 + h) * 16 + i) * 16 + j] = w;   // weight output
    }
  }
  __syncthreads();

  // value projections: avA = tanh(oa.Wv), diff = tanh(op.Wv) - avA
  for (int h = 0; h < 2; ++h) {
    const float4* wv4 = (const float4*)(Wv + (h * 64 + e) * 128);
    float sA[4] = {0,0,0,0}, sP[4] = {0,0,0,0};
#pragma unroll 8
    for (int d4 = 0; d4 < 32; ++d4) {
      float4 w = wv4[d4];
#pragma unroll
      for (int t = 0; t < 4; ++t) {
        int n = ng * 4 + t;
        float4 a = *(const float4*)&oa[n][d4 * 4];
        float4 p = *(const float4*)&op[n][d4 * 4];
        sA[t] += a.x * w.x + a.y * w.y + a.z * w.z + a.w * w.w;
        sP[t] += p.x * w.x + p.y * w.y + p.z * w.z + p.w * w.w;
      }
    }
#pragma unroll
    for (int t = 0; t < 4; ++t) {
      int n = ng * 4 + t;
      float ta = tanhf(sA[t]);
      float tp = tanhf(sP[t]);
      avA[h][n][e] = ta;
      g_diff[((b * 2 + h) * 16 + n) * 64 + e] = tp - ta;
    }
  }
  __syncthreads();

  // base[b,h,i,e] = sum_k w[b,h,i,k] * avA[b,h,k,e]
  for (int o = tid; o < 2048; o += 256) {
    int h = o >> 10, i = (o >> 6) & 15, ee = o & 63;
    float s = 0.f;
#pragma unroll
    for (int k = 0; k < 16; ++k)
      s += wsm[h][i][k] * avA[h][k][ee];
    g_base[((b * 2 + h) * 16 + i) * 64 + ee] = s;
  }
}

// ---------------------------------------------------------------------------
// Stage 2: one block per (b,i). 256 threads. W1 cached in smem (pitch 129 ->
// conflict-free scalar LDS). Thread = 2j x 2n register tile; shuffle-reduce.
// ---------------------------------------------------------------------------
__global__ void __launch_bounds__(256) k_mlp(
    const float* __restrict__ W1, const float* __restrict__ W2,
    float* __restrict__ out)
{
  int b = blockIdx.x >> 4, i = blockIdx.x & 15;
  int t = threadIdx.x;

  __shared__ float w1s[64][129];
  __shared__ float xs[16][129];
  __shared__ float w2s[64];

  // load W1 (coalesced), W2
  for (int idx = t; idx < 64 * 128; idx += 256)
    w1s[idx >> 7][idx & 127] = W1[idx];
  if (t < 64) w2s[t] = W2[t];

  // assemble x[j][hd] for all 16 j:  (base + w*diff)/16 + noise_mean
  for (int idx = t; idx < 2048; idx += 256) {
    int j = idx >> 7, hd = idx & 127;
    int h = hd >> 6, e = hd & 63;
    float w  = out[2048 + ((b * 2 + h) * 16 + i) * 16 + j];
    float bs = g_base[((b * 2 + h) * 16 + i) * 64 + e];
    float df = g_diff[((b * 2 + h) * 16 + j) * 64 + e];
    float nm = g_nm[(((b * 2 + h) * 16 + i) * 16 + j) * 64 + e];
    xs[j][hd] = (bs + w * df) * 0.0625f + nm;
  }
  __syncthreads();

  // warp w handles j pair {2w, 2w+1}; lane l handles neurons {l, l+32}
  int j0 = (t >> 5) * 2;
  int n0 = t & 31;
  float a00 = 0.f, a01 = 0.f, a10 = 0.f, a11 = 0.f;
#pragma unroll 4
  for (int c = 0; c < 128; ++c) {
    float x0 = xs[j0][c];          // warp-uniform broadcast
    float x1 = xs[j0 + 1][c];
    float w0 = w1s[n0][c];         // bank (n0 + c) & 31 -> conflict-free
    float w1 = w1s[n0 + 32][c];
    a00 += w0 * x0; a01 += w0 * x1;
    a10 += w1 * x0; a11 += w1 * x1;
  }
  // leaky relu + W2 weighting, then sum over neurons (warp reduce)
  a00 = (a00 > 0.f ? a00 : 0.01f * a00) * w2s[n0];
  a10 = (a10 > 0.f ? a10 : 0.01f * a10) * w2s[n0 + 32];
  a01 = (a01 > 0.f ? a01 : 0.01f * a01) * w2s[n0];
  a11 = (a11 > 0.f ? a11 : 0.01f * a11) * w2s[n0 + 32];
  float r0 = a00 + a10;            // -> out[b,i,j0]
  float r1 = a01 + a11;            // -> out[b,i,j0+1]
#pragma unroll
  for (int o = 16; o > 0; o >>= 1) {
    r0 += __shfl_down_sync(0xffffffffu, r0, o);
    r1 += __shfl_down_sync(0xffffffffu, r1, o);
  }
  if (n0 == 0) {
    out[(b * 16 + i) * 16 + j0]     = r0;
    out[(b * 16 + i) * 16 + j0 + 1] = r1;
  }
}

// ---------------------------------------------------------------------------
extern "C" void kernel_launch(void* const* d_in, const int* in_sizes, int n_in,
                              void* d_out, int out_size) {
  const float* states   = (const float*)d_in[0];
  const float* policies = (const float*)d_in[1];
  const float* actions  = (const float*)d_in[2];
  const float* Wk       = (const float*)d_in[3];
  const float* Wq       = (const float*)d_in[4];
  const float* Wv       = (const float*)d_in[5];
  const float* W1       = (const float*)d_in[6];
  const float* W2       = (const float*)d_in[7];
  float* out = (float*)d_out;

  // 8 attention blocks + 1024 noise blocks, run concurrently in one launch
  k_stage1<<<8 + 1024, 256>>>(states, policies, actions, Wk, Wq, Wv, out);
  // consumes weight (in out), base/diff/noise scratch
  k_mlp<<<128, 256>>>(W1, W2, out);
}